// round 14
// baseline (speedup 1.0000x reference)
#include <cuda_runtime.h>
#include <math.h>

// Problem constants
#define B_   2
#define H_   1080
#define W_   1920
#define SH_  540
#define SW_  960
#define HW_  (H_*W_)
#define SHW_ (SH_*SW_)

// Scratch (device globals — no allocations allowed)
__device__ float2 g_grad_half[B_*SHW_];

// constant-shift sobel weights (shift = offset*(N-1)/N, always < 1)
#define SXE ((float)(SW_-1)/(float)SW_)        // edge sobel, offset 1.0
#define SYE ((float)(SH_-1)/(float)SH_)
#define SXG (0.5f*(float)(SW_-1)/(float)SW_)   // grad sobel, offset 0.5
#define SYG (0.5f*(float)(SH_-1)/(float)SH_)

// gaussian sigma=1 5-tap
#define GW0 0.4026199469f
#define GW1 0.2442013420f
#define GW2 0.0544886845f

__device__ __forceinline__ int iclamp(int v, int lo, int hi) {
    return min(max(v, lo), hi);
}

// MUFU-based approximate 1/(sqrt(m2)+eps)
__device__ __forceinline__ float inv_len(float m2) {
    float s, r;
    asm("sqrt.approx.f32 %0, %1;" : "=f"(s) : "f"(m2));
    s += 0.01f;
    asm("rcp.approx.f32 %0, %1;" : "=f"(r) : "f"(s));
    return r;
}

// ---- packed f32x2 helpers (Blackwell) ----
typedef unsigned long long u64;
__device__ __forceinline__ u64 pk2(float x, float y) {
    u64 r; asm("mov.b64 %0, {%1, %2};" : "=l"(r) : "f"(x), "f"(y)); return r;
}
__device__ __forceinline__ void upk2(u64 p, float& x, float& y) {
    asm("mov.b64 {%0, %1}, %2;" : "=f"(x), "=f"(y) : "l"(p));
}
__device__ __forceinline__ u64 sub2(u64 a, u64 b) {
    u64 r; asm("sub.rn.f32x2 %0, %1, %2;" : "=l"(r) : "l"(a), "l"(b)); return r;
}
__device__ __forceinline__ u64 fma2(u64 a, u64 b, u64 c) {
    u64 r; asm("fma.rn.f32x2 %0, %1, %2, %3;" : "=l"(r) : "l"(a), "l"(b), "l"(c)); return r;
}

// ---------------------------------------------------------------------------
// k1: fused field kernel on 32x32 tiles (unchanged)
// ---------------------------------------------------------------------------
__global__ void __launch_bounds__(256) k_field(const float* __restrict__ img) {
    __shared__ float sL[40][41];
    __shared__ float sE[38][39];
    __shared__ float sH[38][35];
    __shared__ float sV[34][35];

    int j0 = blockIdx.x * 32;
    int i0 = blockIdx.y * 32;
    int b  = blockIdx.z;
    int tid = threadIdx.y * 32 + threadIdx.x;

    const float* r0c = img + (size_t)b * 3 * HW_;
    const float* g0c = r0c + HW_;
    const float* b0c = r0c + 2 * HW_;

    for (int t = tid; t < 40 * 40; t += 256) {
        int r = t / 40, c = t % 40;
        int hi = iclamp(i0 - 4 + r, 0, SH_ - 1);
        int hj = iclamp(j0 - 4 + c, 0, SW_ - 1);

        float ys = fminf((float)hi * (1079.0f / 539.0f), 1079.0f);
        float xs = fminf((float)hj * (1919.0f / 959.0f), 1919.0f);
        int y0 = (int)ys, x0 = (int)xs;
        int y1 = min(y0 + 1, H_ - 1), x1 = min(x0 + 1, W_ - 1);
        float wy = ys - (float)y0, wx = xs - (float)x0;

        int i00 = y0 * W_ + x0, i01 = y0 * W_ + x1;
        int i10 = y1 * W_ + x0, i11 = y1 * W_ + x1;
        float v00 = 0.299f*__ldg(r0c+i00) + 0.587f*__ldg(g0c+i00) + 0.114f*__ldg(b0c+i00);
        float v01 = 0.299f*__ldg(r0c+i01) + 0.587f*__ldg(g0c+i01) + 0.114f*__ldg(b0c+i01);
        float v10 = 0.299f*__ldg(r0c+i10) + 0.587f*__ldg(g0c+i10) + 0.114f*__ldg(b0c+i10);
        float v11 = 0.299f*__ldg(r0c+i11) + 0.587f*__ldg(g0c+i11) + 0.114f*__ldg(b0c+i11);

        float v = (v00 * (1.f - wx) + v01 * wx) * (1.f - wy)
                + (v10 * (1.f - wx) + v11 * wx) * wy;
        sL[r][c] = v;
    }
    __syncthreads();

    for (int t = tid; t < 38 * 38; t += 256) {
        int er = t / 38, ec = t % 38;
        int ci = iclamp(i0 - 3 + er, 0, SH_ - 1);
        int cj = iclamp(j0 - 3 + ec, 0, SW_ - 1);
        int rm = max(ci - 1, 0)        - (i0 - 4);
        int rc = ci                    - (i0 - 4);
        int rp = min(ci + 1, SH_ - 1)  - (i0 - 4);
        int cm = max(cj - 1, 0)        - (j0 - 4);
        int cc = cj                    - (j0 - 4);
        int cp = min(cj + 1, SW_ - 1)  - (j0 - 4);

        float gxm = SXE * (sL[rm][cp] - sL[rm][cm]);
        float gxc = SXE * (sL[rc][cp] - sL[rc][cm]);
        float gxp = SXE * (sL[rp][cp] - sL[rp][cm]);
        float gsm = SXE * (sL[rm][cm] + sL[rm][cp]) + (4.f - 2.f * SXE) * sL[rm][cc];
        float gsp = SXE * (sL[rp][cm] + sL[rp][cp]) + (4.f - 2.f * SXE) * sL[rp][cc];

        float xg = 0.125f * (SYE * (gxm + gxp) + (4.f - 2.f * SYE) * gxc);
        float yg = 0.125f * SYE * (gsp - gsm);
        float m2 = xg * xg + yg * yg;
        sE[er][ec] = exp2f(0.35f * __log2f(m2));
    }
    __syncthreads();

    for (int t = tid; t < 38 * 34; t += 256) {
        int hr = t / 34, hc = t % 34;
        int cj = iclamp(j0 - 1 + hc, 0, SW_ - 1);
        int c0 = max(cj - 2, 0)       - (j0 - 3);
        int c1 = max(cj - 1, 0)       - (j0 - 3);
        int c2 = cj                   - (j0 - 3);
        int c3 = min(cj + 1, SW_ - 1) - (j0 - 3);
        int c4 = min(cj + 2, SW_ - 1) - (j0 - 3);
        sH[hr][hc] = GW2 * (sE[hr][c0] + sE[hr][c4])
                   + GW1 * (sE[hr][c1] + sE[hr][c3])
                   + GW0 * sE[hr][c2];
    }
    __syncthreads();

    for (int t = tid; t < 34 * 34; t += 256) {
        int vr = t / 34, hc = t % 34;
        int ci = iclamp(i0 - 1 + vr, 0, SH_ - 1);
        int r0 = max(ci - 2, 0)       - (i0 - 3);
        int r1 = max(ci - 1, 0)       - (i0 - 3);
        int r2 = ci                   - (i0 - 3);
        int r3 = min(ci + 1, SH_ - 1) - (i0 - 3);
        int r4 = min(ci + 2, SH_ - 1) - (i0 - 3);
        sV[vr][hc] = GW2 * (sH[r0][hc] + sH[r4][hc])
                   + GW1 * (sH[r1][hc] + sH[r3][hc])
                   + GW0 * sH[r2][hc];
    }
    __syncthreads();

    for (int t = tid; t < 32 * 32; t += 256) {
        int gr = t / 32, gc = t % 32;
        int i = i0 + gr, j = j0 + gc;
        if (i >= SH_ || j >= SW_) continue;
        int rm = max(i - 1, 0)        - (i0 - 1);
        int rc = i                    - (i0 - 1);
        int rp = min(i + 1, SH_ - 1)  - (i0 - 1);
        int cm = max(j - 1, 0)        - (j0 - 1);
        int cc = j                    - (j0 - 1);
        int cp = min(j + 1, SW_ - 1)  - (j0 - 1);

        float gxm = SXG * (sV[rm][cp] - sV[rm][cm]);
        float gxc = SXG * (sV[rc][cp] - sV[rc][cm]);
        float gxp = SXG * (sV[rp][cp] - sV[rp][cm]);
        float gsm = SXG * (sV[rm][cm] + sV[rm][cp]) + (4.f - 2.f * SXG) * sV[rm][cc];
        float gsp = SXG * (sV[rp][cm] + sV[rp][cp]) + (4.f - 2.f * SXG) * sV[rp][cc];

        float xg = 0.125f * (SYG * (gxm + gxp) + (4.f - 2.f * SYG) * gxc);
        float yg = 0.125f * SYG * (gsp - gsm);
        g_grad_half[(size_t)b * SHW_ + (size_t)i * SW_ + j] = make_float2(xg, yg);
    }
}

// ---------------------------------------------------------------------------
// k2: fused resize + warp + sample, 32x32 tile, 4 px/thread.
//     PAIRED-CORNER lattice layout: sg4[sy][sx] = (v(sx), v(sx+1)) as float4,
//     so both x-corners of a row come from ONE aligned LDS.128.
//     Hot loop: 2 LDS.128 + packed-f32x2 bilinear + MUFU normalize.
// ---------------------------------------------------------------------------
#define SMW 34   // lattice columns 0..33
#define SMH 34   // lattice rows 0..33
#define SG4W 34  // sg4 row width (33 used + 1 pad)

template<bool INTR>
__device__ __forceinline__ void warp_iters(
    const float4 (*sg4)[SG4W],
    float fx[4], float fy[4],
    const float cy0[4], const float cy1[4], const int yb[4],
    int tx, float cx0, float cx1,
    float floX, float fhiX, float floY, float fhiY,
    float stx, float sty)
{
#pragma unroll
    for (int it = 0; it < 6; it++) {
#pragma unroll
        for (int s = 0; s < 4; s++) {
            float xc = fx[s], yc = fy[s];
            if (!INTR) {
                xc = fminf(fmaxf(xc, floX), fhiX);
                yc = fminf(fmaxf(yc, floY), fhiY);
            }
            bool bx = xc >= cx1;
            bool by = yc >= cy1[s];
            float wx = xc - (bx ? cx1 : cx0);
            float wy = yc - (by ? cy1[s] : cy0[s]);
            int sx0 = tx + (bx ? 1 : 0);
            int sy0 = yb[s] + (by ? 1 : 0);

            float4 q0 = sg4[sy0][sx0];       // (v00, v01) — one LDS.128
            float4 q1 = sg4[sy0 + 1][sx0];   // (v10, v11)
            u64 v00 = pk2(q0.x, q0.y), v01 = pk2(q0.z, q0.w);
            u64 v10 = pk2(q1.x, q1.y), v11 = pk2(q1.z, q1.w);

            u64 wxp = pk2(wx, wx);
            u64 wyp = pk2(wy, wy);
            u64 top = fma2(wxp, sub2(v01, v00), v00);
            u64 bot = fma2(wxp, sub2(v11, v10), v10);
            u64 res = fma2(wyp, sub2(bot, top), top);

            float dx, dy;
            upk2(res, dx, dy);
            float inv = inv_len(dx * dx + dy * dy);
            fx[s] -= (dx * inv) * stx;
            fy[s] -= (dy * inv) * sty;
        }
    }
}

__global__ void __launch_bounds__(256, 7) k_warp_fused(const float* __restrict__ img,
                                                       float* __restrict__ out) {
    __shared__ float4 sg4[SMH][SG4W];   // ~18.5 KB

    int j0 = blockIdx.x * 32;
    int i0 = blockIdx.y * 32;
    int b  = blockIdx.z;
    int tx = threadIdx.x, ty = threadIdx.y;
    int tid = ty * 32 + tx;

    const float2* gh = g_grad_half + (size_t)b * SHW_;

    // fill lattice patch [i0-1, i0+32] x [j0-1, j0+32]; each point stored
    // twice: as lo-half of its own column and hi-half of the column left.
    for (int t = tid; t < SMW * SMH; t += 256) {
        int sy = t / SMW, sx = t % SMW;
        int I = iclamp(i0 - 1 + sy, 0, H_ - 1);
        int J = iclamp(j0 - 1 + sx, 0, W_ - 1);

        float ys = fminf((float)I * (539.0f / 1079.0f), (float)(SH_ - 1));
        float xs = fminf((float)J * (959.0f / 1919.0f), (float)(SW_ - 1));
        int y0 = (int)ys, x0 = (int)xs;
        int y1 = min(y0 + 1, SH_ - 1), x1 = min(x0 + 1, SW_ - 1);
        float wy = ys - (float)y0, wx = xs - (float)x0;

        float2 v00 = __ldg(&gh[(size_t)y0 * SW_ + x0]);
        float2 v01 = __ldg(&gh[(size_t)y0 * SW_ + x1]);
        float2 v10 = __ldg(&gh[(size_t)y1 * SW_ + x0]);
        float2 v11 = __ldg(&gh[(size_t)y1 * SW_ + x1]);
        float rx = (v00.x * (1.f - wx) + v01.x * wx) * (1.f - wy)
                 + (v10.x * (1.f - wx) + v11.x * wx) * wy;
        float ry = (v00.y * (1.f - wx) + v01.y * wx) * (1.f - wy)
                 + (v10.y * (1.f - wx) + v11.y * wx) * wy;

        u64 rp = pk2(rx, ry);
        if (sx <= 32) *reinterpret_cast<u64*>(&sg4[sy][sx])         = rp;  // lo half
        if (sx >= 1)  *(reinterpret_cast<u64*>(&sg4[sy][sx - 1]) + 1) = rp; // hi half
    }
    __syncthreads();

    const float stx = 0.1f * (float)(W_ - 1) / (float)W_;
    const float sty = 0.1f * (float)(H_ - 1) / (float)H_;

    const float floX = (float)(1 - j0), fhiX = (float)(W_ - j0);
    const float floY = (float)(1 - i0), fhiY = (float)(H_ - i0);

    const float cx0 = (float)tx, cx1 = cx0 + 1.0f;

    float fx[4], fy[4], cy0[4], cy1[4];
    int   yb[4];
#pragma unroll
    for (int s = 0; s < 4; s++) {
        yb[s]  = ty + s * 8;
        cy0[s] = (float)yb[s];
        cy1[s] = cy0[s] + 1.0f;
        fx[s] = cx1;
        fy[s] = cy1[s];
    }

    bool intr = (blockIdx.x > 0) && (blockIdx.x < gridDim.x - 1)
             && (blockIdx.y > 0) && (blockIdx.y < gridDim.y - 1);
    if (intr)
        warp_iters<true >(sg4, fx, fy, cy0, cy1, yb, tx, cx0, cx1,
                          floX, fhiX, floY, fhiY, stx, sty);
    else
        warp_iters<false>(sg4, fx, fy, cy0, cy1, yb, tx, cx0, cx1,
                          floX, fhiX, floY, fhiY, stx, sty);

    // final image sample (3 channels, global/L1) + clip, all 4 rows
    int j = j0 + tx;
#pragma unroll
    for (int s = 0; s < 4; s++) {
        int i = i0 + yb[s];
        if (i >= H_) break;

        float px = fx[s] + (float)(j0 - 1);
        float py = fy[s] + (float)(i0 - 1);
        float xc = fminf(fmaxf(px, 0.f), (float)(W_ - 1));
        float yc = fminf(fmaxf(py, 0.f), (float)(H_ - 1));
        int x0 = (int)xc, y0 = (int)yc;
        int x1 = min(x0 + 1, W_ - 1), y1 = min(y0 + 1, H_ - 1);
        float wx = xc - (float)x0, wy = yc - (float)y0;
        float w00 = (1.f - wx) * (1.f - wy), w01 = wx * (1.f - wy);
        float w10 = (1.f - wx) * wy,         w11 = wx * wy;
        size_t i00 = (size_t)y0 * W_ + x0, i01 = (size_t)y0 * W_ + x1;
        size_t i10 = (size_t)y1 * W_ + x0, i11 = (size_t)y1 * W_ + x1;

#pragma unroll
        for (int c = 0; c < 3; c++) {
            const float* plane = img + ((size_t)b * 3 + c) * HW_;
            float v = __ldg(plane + i00) * w00 + __ldg(plane + i01) * w01
                    + __ldg(plane + i10) * w10 + __ldg(plane + i11) * w11;
            v = fminf(fmaxf(v, 0.f), 1.f);
            out[((size_t)b * 3 + c) * HW_ + (size_t)i * W_ + j] = v;
        }
    }
}

// ---------------------------------------------------------------------------
extern "C" void kernel_launch(void* const* d_in, const int* in_sizes, int n_in,
                              void* d_out, int out_size) {
    const float* img = (const float*)d_in[0];
    float* out = (float*)d_out;

    dim3 blk(32, 8, 1);
    dim3 gridS((SW_ + 31) / 32, (SH_ + 31) / 32, B_);
    dim3 gridF(W_ / 32, (H_ + 31) / 32, B_);

    k_field     <<<gridS, blk>>>(img);
    k_warp_fused<<<gridF, blk>>>(img, out);
}

// round 16
// speedup vs baseline: 1.0430x; 1.0430x over previous
#include <cuda_runtime.h>
#include <math.h>

// Problem constants
#define B_   2
#define H_   1080
#define W_   1920
#define SH_  540
#define SW_  960
#define HW_  (H_*W_)
#define SHW_ (SH_*SW_)

// Scratch (device globals — no allocations allowed)
__device__ float2 g_grad_half[B_*SHW_];

// constant-shift sobel weights (shift = offset*(N-1)/N, always < 1)
#define SXE ((float)(SW_-1)/(float)SW_)        // edge sobel, offset 1.0
#define SYE ((float)(SH_-1)/(float)SH_)
#define SXG (0.5f*(float)(SW_-1)/(float)SW_)   // grad sobel, offset 0.5
#define SYG (0.5f*(float)(SH_-1)/(float)SH_)

// gaussian sigma=1 5-tap
#define GW0 0.4026199469f
#define GW1 0.2442013420f
#define GW2 0.0544886845f

__device__ __forceinline__ int iclamp(int v, int lo, int hi) {
    return min(max(v, lo), hi);
}

// MUFU-based approximate 1/(sqrt(m2)+eps)
__device__ __forceinline__ float inv_len(float m2) {
    float s, r;
    asm("sqrt.approx.f32 %0, %1;" : "=f"(s) : "f"(m2));
    s += 0.01f;
    asm("rcp.approx.f32 %0, %1;" : "=f"(r) : "f"(s));
    return r;
}

// ---- packed f32x2 helpers (Blackwell) ----
typedef unsigned long long u64;
__device__ __forceinline__ u64 pk2(float x, float y) {
    u64 r; asm("mov.b64 %0, {%1, %2};" : "=l"(r) : "f"(x), "f"(y)); return r;
}
__device__ __forceinline__ void upk2(u64 p, float& x, float& y) {
    asm("mov.b64 {%0, %1}, %2;" : "=f"(x), "=f"(y) : "l"(p));
}
__device__ __forceinline__ u64 sub2(u64 a, u64 b) {
    u64 r; asm("sub.rn.f32x2 %0, %1, %2;" : "=l"(r) : "l"(a), "l"(b)); return r;
}
__device__ __forceinline__ u64 fma2(u64 a, u64 b, u64 c) {
    u64 r; asm("fma.rn.f32x2 %0, %1, %2, %3;" : "=l"(r) : "l"(a), "l"(b), "l"(c)); return r;
}

// ---------------------------------------------------------------------------
// k1: fused field kernel on 32x32 tiles (unchanged)
// ---------------------------------------------------------------------------
__global__ void __launch_bounds__(256) k_field(const float* __restrict__ img) {
    __shared__ float sL[40][41];
    __shared__ float sE[38][39];
    __shared__ float sH[38][35];
    __shared__ float sV[34][35];

    int j0 = blockIdx.x * 32;
    int i0 = blockIdx.y * 32;
    int b  = blockIdx.z;
    int tid = threadIdx.y * 32 + threadIdx.x;

    const float* r0c = img + (size_t)b * 3 * HW_;
    const float* g0c = r0c + HW_;
    const float* b0c = r0c + 2 * HW_;

    for (int t = tid; t < 40 * 40; t += 256) {
        int r = t / 40, c = t % 40;
        int hi = iclamp(i0 - 4 + r, 0, SH_ - 1);
        int hj = iclamp(j0 - 4 + c, 0, SW_ - 1);

        float ys = fminf((float)hi * (1079.0f / 539.0f), 1079.0f);
        float xs = fminf((float)hj * (1919.0f / 959.0f), 1919.0f);
        int y0 = (int)ys, x0 = (int)xs;
        int y1 = min(y0 + 1, H_ - 1), x1 = min(x0 + 1, W_ - 1);
        float wy = ys - (float)y0, wx = xs - (float)x0;

        int i00 = y0 * W_ + x0, i01 = y0 * W_ + x1;
        int i10 = y1 * W_ + x0, i11 = y1 * W_ + x1;
        float v00 = 0.299f*__ldg(r0c+i00) + 0.587f*__ldg(g0c+i00) + 0.114f*__ldg(b0c+i00);
        float v01 = 0.299f*__ldg(r0c+i01) + 0.587f*__ldg(g0c+i01) + 0.114f*__ldg(b0c+i01);
        float v10 = 0.299f*__ldg(r0c+i10) + 0.587f*__ldg(g0c+i10) + 0.114f*__ldg(b0c+i10);
        float v11 = 0.299f*__ldg(r0c+i11) + 0.587f*__ldg(g0c+i11) + 0.114f*__ldg(b0c+i11);

        float v = (v00 * (1.f - wx) + v01 * wx) * (1.f - wy)
                + (v10 * (1.f - wx) + v11 * wx) * wy;
        sL[r][c] = v;
    }
    __syncthreads();

    for (int t = tid; t < 38 * 38; t += 256) {
        int er = t / 38, ec = t % 38;
        int ci = iclamp(i0 - 3 + er, 0, SH_ - 1);
        int cj = iclamp(j0 - 3 + ec, 0, SW_ - 1);
        int rm = max(ci - 1, 0)        - (i0 - 4);
        int rc = ci                    - (i0 - 4);
        int rp = min(ci + 1, SH_ - 1)  - (i0 - 4);
        int cm = max(cj - 1, 0)        - (j0 - 4);
        int cc = cj                    - (j0 - 4);
        int cp = min(cj + 1, SW_ - 1)  - (j0 - 4);

        float gxm = SXE * (sL[rm][cp] - sL[rm][cm]);
        float gxc = SXE * (sL[rc][cp] - sL[rc][cm]);
        float gxp = SXE * (sL[rp][cp] - sL[rp][cm]);
        float gsm = SXE * (sL[rm][cm] + sL[rm][cp]) + (4.f - 2.f * SXE) * sL[rm][cc];
        float gsp = SXE * (sL[rp][cm] + sL[rp][cp]) + (4.f - 2.f * SXE) * sL[rp][cc];

        float xg = 0.125f * (SYE * (gxm + gxp) + (4.f - 2.f * SYE) * gxc);
        float yg = 0.125f * SYE * (gsp - gsm);
        float m2 = xg * xg + yg * yg;
        sE[er][ec] = exp2f(0.35f * __log2f(m2));
    }
    __syncthreads();

    for (int t = tid; t < 38 * 34; t += 256) {
        int hr = t / 34, hc = t % 34;
        int cj = iclamp(j0 - 1 + hc, 0, SW_ - 1);
        int c0 = max(cj - 2, 0)       - (j0 - 3);
        int c1 = max(cj - 1, 0)       - (j0 - 3);
        int c2 = cj                   - (j0 - 3);
        int c3 = min(cj + 1, SW_ - 1) - (j0 - 3);
        int c4 = min(cj + 2, SW_ - 1) - (j0 - 3);
        sH[hr][hc] = GW2 * (sE[hr][c0] + sE[hr][c4])
                   + GW1 * (sE[hr][c1] + sE[hr][c3])
                   + GW0 * sE[hr][c2];
    }
    __syncthreads();

    for (int t = tid; t < 34 * 34; t += 256) {
        int vr = t / 34, hc = t % 34;
        int ci = iclamp(i0 - 1 + vr, 0, SH_ - 1);
        int r0 = max(ci - 2, 0)       - (i0 - 3);
        int r1 = max(ci - 1, 0)       - (i0 - 3);
        int r2 = ci                   - (i0 - 3);
        int r3 = min(ci + 1, SH_ - 1) - (i0 - 3);
        int r4 = min(ci + 2, SH_ - 1) - (i0 - 3);
        sV[vr][hc] = GW2 * (sH[r0][hc] + sH[r4][hc])
                   + GW1 * (sH[r1][hc] + sH[r3][hc])
                   + GW0 * sH[r2][hc];
    }
    __syncthreads();

    for (int t = tid; t < 32 * 32; t += 256) {
        int gr = t / 32, gc = t % 32;
        int i = i0 + gr, j = j0 + gc;
        if (i >= SH_ || j >= SW_) continue;
        int rm = max(i - 1, 0)        - (i0 - 1);
        int rc = i                    - (i0 - 1);
        int rp = min(i + 1, SH_ - 1)  - (i0 - 1);
        int cm = max(j - 1, 0)        - (j0 - 1);
        int cc = j                    - (j0 - 1);
        int cp = min(j + 1, SW_ - 1)  - (j0 - 1);

        float gxm = SXG * (sV[rm][cp] - sV[rm][cm]);
        float gxc = SXG * (sV[rc][cp] - sV[rc][cm]);
        float gxp = SXG * (sV[rp][cp] - sV[rp][cm]);
        float gsm = SXG * (sV[rm][cm] + sV[rm][cp]) + (4.f - 2.f * SXG) * sV[rm][cc];
        float gsp = SXG * (sV[rp][cm] + sV[rp][cp]) + (4.f - 2.f * SXG) * sV[rp][cc];

        float xg = 0.125f * (SYG * (gxm + gxp) + (4.f - 2.f * SYG) * gxc);
        float yg = 0.125f * SYG * (gsp - gsm);
        g_grad_half[(size_t)b * SHW_ + (size_t)i * SW_ + j] = make_float2(xg, yg);
    }
}

// ---------------------------------------------------------------------------
// k2: fused resize + warp + sample, 32x32 tile, 4 px/thread (R13 shape).
//     Iteration 0 collapses exactly: position == own lattice point, so
//     wx=wy=0 and the bilinear is a single LDS.64 of sg[yb+1][tx+1].
//     Iterations 1..5 use the proven lattice-local + packed-f32x2 body.
// ---------------------------------------------------------------------------
#define SMW 34
#define SMH 34

template<bool INTR>
__device__ __forceinline__ void warp_iters(
    const float2 (*sg)[SMW],
    float fx[4], float fy[4],
    const float cy0[4], const float cy1[4], const int yb[4],
    int tx, float cx0, float cx1,
    float floX, float fhiX, float floY, float fhiY,
    float stx, float sty)
{
    // ---- iteration 0: exact collapse (wx=wy=0 at own lattice point) ----
#pragma unroll
    for (int s = 0; s < 4; s++) {
        float2 d = sg[yb[s] + 1][tx + 1];
        float inv = inv_len(d.x * d.x + d.y * d.y);
        fx[s] -= (d.x * inv) * stx;
        fy[s] -= (d.y * inv) * sty;
    }

    // ---- iterations 1..5 ----
#pragma unroll
    for (int it = 1; it < 6; it++) {
#pragma unroll
        for (int s = 0; s < 4; s++) {
            float xc = fx[s], yc = fy[s];
            if (!INTR) {
                xc = fminf(fmaxf(xc, floX), fhiX);
                yc = fminf(fmaxf(yc, floY), fhiY);
            }
            bool bx = xc >= cx1;
            bool by = yc >= cy1[s];
            float wx = xc - (bx ? cx1 : cx0);
            float wy = yc - (by ? cy1[s] : cy0[s]);
            int sx0 = tx + (bx ? 1 : 0);
            int sy0 = yb[s] + (by ? 1 : 0);

            u64 v00 = *reinterpret_cast<const u64*>(&sg[sy0][sx0]);
            u64 v01 = *reinterpret_cast<const u64*>(&sg[sy0][sx0 + 1]);
            u64 v10 = *reinterpret_cast<const u64*>(&sg[sy0 + 1][sx0]);
            u64 v11 = *reinterpret_cast<const u64*>(&sg[sy0 + 1][sx0 + 1]);

            u64 wxp = pk2(wx, wx);
            u64 wyp = pk2(wy, wy);
            u64 top = fma2(wxp, sub2(v01, v00), v00);
            u64 bot = fma2(wxp, sub2(v11, v10), v10);
            u64 res = fma2(wyp, sub2(bot, top), top);

            float dx, dy;
            upk2(res, dx, dy);
            float inv = inv_len(dx * dx + dy * dy);
            fx[s] -= (dx * inv) * stx;
            fy[s] -= (dy * inv) * sty;
        }
    }
}

__global__ void __launch_bounds__(256, 7) k_warp_fused(const float* __restrict__ img,
                                                       float* __restrict__ out) {
    __shared__ float2 sg[SMH][SMW];

    int j0 = blockIdx.x * 32;
    int i0 = blockIdx.y * 32;
    int b  = blockIdx.z;
    int tx = threadIdx.x, ty = threadIdx.y;
    int tid = ty * 32 + tx;

    const float2* gh = g_grad_half + (size_t)b * SHW_;

    // fill full-res grad lattice patch [i0-1, i0+32] x [j0-1, j0+32]
    for (int t = tid; t < SMW * SMH; t += 256) {
        int sy = t / SMW, sx = t % SMW;
        int I = iclamp(i0 - 1 + sy, 0, H_ - 1);
        int J = iclamp(j0 - 1 + sx, 0, W_ - 1);

        float ys = fminf((float)I * (539.0f / 1079.0f), (float)(SH_ - 1));
        float xs = fminf((float)J * (959.0f / 1919.0f), (float)(SW_ - 1));
        int y0 = (int)ys, x0 = (int)xs;
        int y1 = min(y0 + 1, SH_ - 1), x1 = min(x0 + 1, SW_ - 1);
        float wy = ys - (float)y0, wx = xs - (float)x0;

        float2 v00 = __ldg(&gh[(size_t)y0 * SW_ + x0]);
        float2 v01 = __ldg(&gh[(size_t)y0 * SW_ + x1]);
        float2 v10 = __ldg(&gh[(size_t)y1 * SW_ + x0]);
        float2 v11 = __ldg(&gh[(size_t)y1 * SW_ + x1]);
        float2 r;
        r.x = (v00.x * (1.f - wx) + v01.x * wx) * (1.f - wy)
            + (v10.x * (1.f - wx) + v11.x * wx) * wy;
        r.y = (v00.y * (1.f - wx) + v01.y * wx) * (1.f - wy)
            + (v10.y * (1.f - wx) + v11.y * wx) * wy;
        sg[sy][sx] = r;
    }
    __syncthreads();

    const float stx = 0.1f * (float)(W_ - 1) / (float)W_;
    const float sty = 0.1f * (float)(H_ - 1) / (float)H_;

    const float floX = (float)(1 - j0), fhiX = (float)(W_ - j0);
    const float floY = (float)(1 - i0), fhiY = (float)(H_ - i0);

    const float cx0 = (float)tx, cx1 = cx0 + 1.0f;

    float fx[4], fy[4], cy0[4], cy1[4];
    int   yb[4];
#pragma unroll
    for (int s = 0; s < 4; s++) {
        yb[s]  = ty + s * 8;
        cy0[s] = (float)yb[s];
        cy1[s] = cy0[s] + 1.0f;
        fx[s] = cx1;
        fy[s] = cy1[s];
    }

    bool intr = (blockIdx.x > 0) && (blockIdx.x < gridDim.x - 1)
             && (blockIdx.y > 0) && (blockIdx.y < gridDim.y - 1);
    if (intr)
        warp_iters<true >(sg, fx, fy, cy0, cy1, yb, tx, cx0, cx1,
                          floX, fhiX, floY, fhiY, stx, sty);
    else
        warp_iters<false>(sg, fx, fy, cy0, cy1, yb, tx, cx0, cx1,
                          floX, fhiX, floY, fhiY, stx, sty);

    // final image sample (3 channels, global/L1) + clip, all 4 rows
    int j = j0 + tx;
#pragma unroll
    for (int s = 0; s < 4; s++) {
        int i = i0 + yb[s];
        if (i >= H_) break;

        float px = fx[s] + (float)(j0 - 1);
        float py = fy[s] + (float)(i0 - 1);
        float xc = fminf(fmaxf(px, 0.f), (float)(W_ - 1));
        float yc = fminf(fmaxf(py, 0.f), (float)(H_ - 1));
        int x0 = (int)xc, y0 = (int)yc;
        int x1 = min(x0 + 1, W_ - 1), y1 = min(y0 + 1, H_ - 1);
        float wx = xc - (float)x0, wy = yc - (float)y0;
        float w00 = (1.f - wx) * (1.f - wy), w01 = wx * (1.f - wy);
        float w10 = (1.f - wx) * wy,         w11 = wx * wy;
        size_t i00 = (size_t)y0 * W_ + x0, i01 = (size_t)y0 * W_ + x1;
        size_t i10 = (size_t)y1 * W_ + x0, i11 = (size_t)y1 * W_ + x1;

#pragma unroll
        for (int c = 0; c < 3; c++) {
            const float* plane = img + ((size_t)b * 3 + c) * HW_;
            float v = __ldg(plane + i00) * w00 + __ldg(plane + i01) * w01
                    + __ldg(plane + i10) * w10 + __ldg(plane + i11) * w11;
            v = fminf(fmaxf(v, 0.f), 1.f);
            out[((size_t)b * 3 + c) * HW_ + (size_t)i * W_ + j] = v;
        }
    }
}

// ---------------------------------------------------------------------------
extern "C" void kernel_launch(void* const* d_in, const int* in_sizes, int n_in,
                              void* d_out, int out_size) {
    const float* img = (const float*)d_in[0];
    float* out = (float*)d_out;

    dim3 blk(32, 8, 1);
    dim3 gridS((SW_ + 31) / 32, (SH_ + 31) / 32, B_);
    dim3 gridF(W_ / 32, (H_ + 31) / 32, B_);

    k_field     <<<gridS, blk>>>(img);
    k_warp_fused<<<gridF, blk>>>(img, out);
}